// round 1
// baseline (speedup 1.0000x reference)
#include <cuda_runtime.h>
#include <cstdint>

#define NNODES 32768
#define NEDGES 262144
#define CC 128
#define NOUTR 8192
#define NVROWS 24576
#define NAROWS 8192

// ------------------------- scratch (static device, no allocs) -------------------------
__device__ float g_X  [NNODES*CC];
__device__ float g_XAG[NNODES*CC];
__device__ float g_XV2[NNODES*CC];
__device__ float g_UVA[NNODES*256];
__device__ float g_UVB[NNODES*768];
__device__ float g_H  [NNODES*CC];
__device__ float g_CAT[NOUTR*256];
__device__ float g_ARES[NNODES];
__device__ int   g_cnt[NNODES];
__device__ int   g_rowoff[NNODES+1];
__device__ int   g_cursor[NNODES];
__device__ int   g_esrc[NEDGES];
__device__ int   g_eattr[NEDGES];
__device__ float g_WUVA[CC*256];
__device__ float g_BUVA[256];
__device__ float g_WUVB[CC*768];
__device__ float g_BUVB[768];
__device__ float g_WCAT[256*CC];

// ------------------------- small helpers -------------------------
__device__ __forceinline__ float4 f4max(float4 a, float4 b){
    return make_float4(fmaxf(a.x,b.x),fmaxf(a.y,b.y),fmaxf(a.z,b.z),fmaxf(a.w,b.w));
}
__device__ __forceinline__ float4 f4relu(float4 a){
    return make_float4(fmaxf(a.x,0.f),fmaxf(a.y,0.f),fmaxf(a.z,0.f),fmaxf(a.w,0.f));
}

// ------------------------- CSR build -------------------------
__global__ void zero_cnt_kernel(){
    int i = blockIdx.x*blockDim.x + threadIdx.x;
    if (i < NNODES) g_cnt[i] = 0;
}

__global__ void hist_kernel(const int* __restrict__ ei){
    int e = blockIdx.x*blockDim.x + threadIdx.x;
    if (e < NEDGES) atomicAdd(&g_cnt[ei[NEDGES + e]], 1);
}

__global__ void scan_kernel(){
    __shared__ int sh[1024];
    int tid = threadIdx.x;
    int base = tid * 32;
    int s = 0;
    #pragma unroll
    for (int j = 0; j < 32; j++) s += g_cnt[base + j];
    sh[tid] = s;
    __syncthreads();
    int own = s;
    for (int off = 1; off < 1024; off <<= 1){
        int v = (tid >= off) ? sh[tid - off] : 0;
        __syncthreads();
        sh[tid] += v;
        __syncthreads();
    }
    int run = sh[tid] - own;   // exclusive prefix
    for (int j = 0; j < 32; j++){
        g_rowoff[base + j] = run;
        g_cursor[base + j] = run;
        run += g_cnt[base + j];
    }
    if (tid == 1023) g_rowoff[NNODES] = run;
}

__global__ void scatter_kernel(const int* __restrict__ ei, const int* __restrict__ ea){
    int e = blockIdx.x*blockDim.x + threadIdx.x;
    if (e < NEDGES){
        int d = ei[NEDGES + e];
        int p = atomicAdd(&g_cursor[d], 1);
        g_esrc[p]  = ei[e];
        g_eattr[p] = ea[e];
    }
}

// ------------------------- weight prep -------------------------
// Wu = W1_top - W1_bot, Wv = W1_bot; b1 folded into u-bias; WCAT = [Wl; Wr]
__global__ void prep_kernel(const float* __restrict__ ecA_W1, const float* __restrict__ ecA_b1,
                            const float* __restrict__ ec1_W1, const float* __restrict__ ec1_b1,
                            const float* __restrict__ ec2_W1, const float* __restrict__ ec2_b1,
                            const float* __restrict__ ec3_W1, const float* __restrict__ ec3_b1,
                            const float* __restrict__ Wl, const float* __restrict__ Wr){
    int id = blockIdx.x*blockDim.x + threadIdx.x;
    if (id < CC*256){
        int k = id >> 8, c = id & 255;
        float v;
        if (c < 128) v = ecA_W1[k*128 + c] - ecA_W1[(128+k)*128 + c];
        else         v = ecA_W1[(128+k)*128 + (c-128)];
        g_WUVA[k*256 + c] = v;
    }
    if (id < CC*768){
        int k = id / 768, c = id % 768;
        int b = c >> 8, cc = c & 255;
        const float* W1 = (b==0)? ec1_W1 : (b==1)? ec2_W1 : ec3_W1;
        float v;
        if (cc < 128) v = W1[k*128 + cc] - W1[(128+k)*128 + cc];
        else          v = W1[(128+k)*128 + (cc-128)];
        g_WUVB[k*768 + c] = v;
    }
    if (id < 256*CC){
        int k = id >> 7, c = id & 127;
        g_WCAT[id] = (k < 128) ? Wl[k*128 + c] : Wr[(k-128)*128 + c];
    }
    if (id < 256) g_BUVA[id] = (id < 128) ? ecA_b1[id] : 0.f;
    if (id < 768){
        int b = id >> 8, cc = id & 255;
        const float* bb = (b==0)? ec1_b1 : (b==1)? ec2_b1 : ec3_b1;
        g_BUVB[id] = (cc < 128) ? bb[cc] : 0.f;
    }
}

// ------------------------- tiled SGEMM: C[M,N] = op(A[M,K] @ B[K,N] + bias) -------------------------
// TM=64, TN=128, TK=16, 256 threads, 4x8 microtile. Requires M%64==0, N%128==0, K%16==0.
template<bool RELU, bool ACC>
__global__ void __launch_bounds__(256) sgemm_kernel(const float* __restrict__ A,
                                                    const float* __restrict__ B,
                                                    const float* __restrict__ bias,
                                                    float* __restrict__ C,
                                                    int M, int N, int K){
    __shared__ float As[16][68];
    __shared__ float Bs[16][128];
    int tid = threadIdx.x;
    int m0 = blockIdx.y * 64;
    int n0 = blockIdx.x * 128;
    int arow = tid >> 2, akq = (tid & 3) * 4;
    int brow = tid >> 5, bc4 = (tid & 31) * 4;
    int tr = tid >> 4, tc = tid & 15;
    float acc[4][8];
    #pragma unroll
    for (int r = 0; r < 4; r++)
        #pragma unroll
        for (int c = 0; c < 8; c++) acc[r][c] = 0.f;

    for (int k0 = 0; k0 < K; k0 += 16){
        float4 a = *(const float4*)(A + (size_t)(m0 + arow)*K + k0 + akq);
        As[akq+0][arow] = a.x; As[akq+1][arow] = a.y;
        As[akq+2][arow] = a.z; As[akq+3][arow] = a.w;
        float4 b0 = *(const float4*)(B + (size_t)(k0 + brow    )*N + n0 + bc4);
        float4 b1 = *(const float4*)(B + (size_t)(k0 + brow + 8)*N + n0 + bc4);
        *(float4*)&Bs[brow    ][bc4] = b0;
        *(float4*)&Bs[brow + 8][bc4] = b1;
        __syncthreads();
        #pragma unroll
        for (int k = 0; k < 16; k++){
            float4 av  = *(const float4*)&As[k][tr*4];
            float4 bv0 = *(const float4*)&Bs[k][tc*8];
            float4 bv1 = *(const float4*)&Bs[k][tc*8 + 4];
            float ar[4] = {av.x, av.y, av.z, av.w};
            float br[8] = {bv0.x, bv0.y, bv0.z, bv0.w, bv1.x, bv1.y, bv1.z, bv1.w};
            #pragma unroll
            for (int r = 0; r < 4; r++)
                #pragma unroll
                for (int c = 0; c < 8; c++)
                    acc[r][c] += ar[r] * br[c];
        }
        __syncthreads();
    }
    #pragma unroll
    for (int r = 0; r < 4; r++){
        int row = m0 + tr*4 + r;
        #pragma unroll
        for (int c = 0; c < 8; c++){
            int col = n0 + tc*8 + c;
            float v = acc[r][c] + bias[col];
            if (RELU) v = fmaxf(v, 0.f);
            size_t idx = (size_t)row * N + col;
            if (ACC) C[idx] += v; else C[idx] = v;
        }
    }
}

// ------------------------- per-node graph kernels (warp per node, CSR) -------------------------
// xa_g = relu(masked seg_max(x_dst + x_src)), empty -> 0
__global__ void vpa_kernel(){
    int w = threadIdx.x >> 5, lane = threadIdx.x & 31;
    int node = blockIdx.x * 8 + w;
    if (node >= NNODES) return;
    const float4* X4 = (const float4*)g_X;
    float4 xd = X4[(size_t)node*32 + lane];
    float4 m = make_float4(-1e30f,-1e30f,-1e30f,-1e30f);
    bool found = false;
    int p = g_rowoff[node], pe = g_rowoff[node+1];
    for (; p < pe; p++){
        if (g_eattr[p] == -3){
            float4 xs = X4[(size_t)g_esrc[p]*32 + lane];
            m = f4max(m, make_float4(xd.x+xs.x, xd.y+xs.y, xd.z+xs.z, xd.w+xs.w));
            found = true;
        }
    }
    float4 o = found ? f4relu(m) : make_float4(0.f,0.f,0.f,0.f);
    ((float4*)g_XAG)[(size_t)node*32 + lane] = o;
}

// xv2 = relu(seg_sum over attr==3 of (ares[src]*x[src] + x[dst]))
__global__ void acv_kernel(){
    int w = threadIdx.x >> 5, lane = threadIdx.x & 31;
    int node = blockIdx.x * 8 + w;
    if (node >= NNODES) return;
    const float4* X4 = (const float4*)g_X;
    float4 xd = X4[(size_t)node*32 + lane];
    float4 acc = make_float4(0.f,0.f,0.f,0.f);
    int p = g_rowoff[node], pe = g_rowoff[node+1];
    for (; p < pe; p++){
        if (g_eattr[p] == 3){
            int s = g_esrc[p];
            float wgt = g_ARES[s];
            float4 xs = X4[(size_t)s*32 + lane];
            acc.x += wgt*xs.x + xd.x;
            acc.y += wgt*xs.y + xd.y;
            acc.z += wgt*xs.z + xd.z;
            acc.w += wgt*xs.w + xd.w;
        }
    }
    ((float4*)g_XV2)[(size_t)node*32 + lane] = f4relu(acc);
}

// k-loop for edge MLP: acc_e[c] += W2[k][c] * t_e[k], batched over CNT edges
template<int CNT>
__device__ __forceinline__ void kdot(const float* __restrict__ W2, int lane,
                                     const float (*ts)[CC], float4 acc[4]){
    #pragma unroll 4
    for (int k = 0; k < CC; k++){
        float4 wv = __ldg((const float4*)(W2 + k*CC + lane*4));
        #pragma unroll
        for (int e = 0; e < CNT; e++){
            float t = ts[e][k];
            acc[e].x += wv.x * t;
            acc[e].y += wv.y * t;
            acc[e].z += wv.z * t;
            acc[e].w += wv.w * t;
        }
    }
}

// EdgeConv core: out = empty ? 0 : relu( max_j( relu(u_i + v_j) @ W2 ) + b2 ); optional fc dot -> ares
__global__ void __launch_bounds__(256) econv_kernel(const float* __restrict__ UV, int ustride,
                                                    int uoff, int voff,
                                                    const float* __restrict__ W2,
                                                    const float* __restrict__ b2,
                                                    int lo, int hi,
                                                    float* __restrict__ Hout,
                                                    const float* __restrict__ fcW,
                                                    const float* __restrict__ fcb,
                                                    float* __restrict__ ares){
    __shared__ float ts[8][4][CC];
    int w = threadIdx.x >> 5, lane = threadIdx.x & 31;
    int node = blockIdx.x * 8 + w;
    if (node >= NNODES) return;
    float4 u = *(const float4*)(UV + (size_t)node*ustride + uoff + lane*4);
    float4 macc = make_float4(-1e30f,-1e30f,-1e30f,-1e30f);
    bool found = false;
    int p = g_rowoff[node], pe = g_rowoff[node+1];
    while (p < pe){
        int srcs[4]; int cnt = 0;
        while (p < pe && cnt < 4){
            int a = g_eattr[p];
            if (a >= lo && a <= hi) srcs[cnt++] = g_esrc[p];
            p++;
        }
        if (cnt == 0) break;
        for (int e = 0; e < cnt; e++){
            float4 v = *(const float4*)(UV + (size_t)srcs[e]*ustride + voff + lane*4);
            float4 t = f4relu(make_float4(u.x+v.x, u.y+v.y, u.z+v.z, u.w+v.w));
            *(float4*)&ts[w][e][lane*4] = t;
        }
        __syncwarp();
        float4 acc[4];
        #pragma unroll
        for (int e = 0; e < 4; e++) acc[e] = make_float4(0.f,0.f,0.f,0.f);
        const float (*tw)[CC] = (const float (*)[CC])ts[w];
        switch (cnt){
            case 1: kdot<1>(W2, lane, tw, acc); break;
            case 2: kdot<2>(W2, lane, tw, acc); break;
            case 3: kdot<3>(W2, lane, tw, acc); break;
            default: kdot<4>(W2, lane, tw, acc); break;
        }
        for (int e = 0; e < cnt; e++) macc = f4max(macc, acc[e]);
        found = true;
        __syncwarp();
    }
    float4 r;
    if (found){
        float4 bb = *(const float4*)(b2 + lane*4);
        r = f4relu(make_float4(macc.x+bb.x, macc.y+bb.y, macc.z+bb.z, macc.w+bb.w));
    } else {
        r = make_float4(0.f,0.f,0.f,0.f);
    }
    if (Hout) *(float4*)(Hout + (size_t)node*CC + lane*4) = r;
    if (ares){
        float part = r.x*fcW[lane*4] + r.y*fcW[lane*4+1] + r.z*fcW[lane*4+2] + r.w*fcW[lane*4+3];
        #pragma unroll
        for (int o = 16; o > 0; o >>= 1) part += __shfl_down_sync(0xffffffffu, part, o);
        if (lane == 0) ares[node] = part + fcb[0];
    }
}

// CAT[r] = [ mean over masked in-edges of H[src] | H[node] ], node = speaker-gathered row
__global__ void cat_kernel(const int* __restrict__ spkp, int lo, int hi){
    int w = threadIdx.x >> 5, lane = threadIdx.x & 31;
    int r = blockIdx.x * 8 + w;
    if (r >= NOUTR) return;
    int spk = spkp ? spkp[0] : 3;
    int node = (r >> 7) * spk * 128 + (r & 127);
    const float4* H4 = (const float4*)g_H;
    float4 s = make_float4(0.f,0.f,0.f,0.f);
    int cnt = 0;
    int p = g_rowoff[node], pe = g_rowoff[node+1];
    for (; p < pe; p++){
        int a = g_eattr[p];
        if (a >= lo && a <= hi){
            float4 hs = H4[(size_t)g_esrc[p]*32 + lane];
            s.x += hs.x; s.y += hs.y; s.z += hs.z; s.w += hs.w;
            cnt++;
        }
    }
    float inv = cnt ? 1.f/(float)cnt : 0.f;
    float4* C4 = (float4*)g_CAT;
    C4[(size_t)r*64 + lane]      = make_float4(s.x*inv, s.y*inv, s.z*inv, s.w*inv);
    C4[(size_t)r*64 + 32 + lane] = H4[(size_t)node*32 + lane];
}

// ------------------------- launch -------------------------
extern "C" void kernel_launch(void* const* d_in, const int* in_sizes, int n_in,
                              void* d_out, int out_size){
    const float* x_visual = (const float*)d_in[0];
    const float* x_audio  = (const float*)d_in[1];
    const float* W011 = (const float*)d_in[2];
    const float* b011 = (const float*)d_in[3];
    const float* W012 = (const float*)d_in[4];
    const float* b012 = (const float*)d_in[5];
    const float* ecA_W1 = (const float*)d_in[6];
    const float* ecA_b1 = (const float*)d_in[7];
    const float* ecA_W2 = (const float*)d_in[8];
    const float* ecA_b2 = (const float*)d_in[9];
    const float* ec1_W1 = (const float*)d_in[10];
    const float* ec1_b1 = (const float*)d_in[11];
    const float* ec1_W2 = (const float*)d_in[12];
    const float* ec1_b2 = (const float*)d_in[13];
    const float* ec2_W1 = (const float*)d_in[14];
    const float* ec2_b1 = (const float*)d_in[15];
    const float* ec2_W2 = (const float*)d_in[16];
    const float* ec2_b2 = (const float*)d_in[17];
    const float* ec3_W1 = (const float*)d_in[18];
    const float* ec3_b1 = (const float*)d_in[19];
    const float* ec3_W2 = (const float*)d_in[20];
    const float* ec3_b2 = (const float*)d_in[21];
    const float* sage_Wl = (const float*)d_in[22];
    const float* sage_bl = (const float*)d_in[23];
    const float* sage_Wr = (const float*)d_in[24];
    const float* fc_W = (const float*)d_in[25];
    const float* fc_b = (const float*)d_in[26];
    const int* edge_index = (const int*)d_in[27];
    const int* edge_attr  = (const int*)d_in[28];
    const int* speakers   = (n_in > 29) ? (const int*)d_in[29] : nullptr;
    float* out = (float*)d_out;

    float *pX, *pXAG, *pXV2, *pUVA, *pUVB, *pH, *pCAT, *pARES;
    float *pWUVA, *pBUVA, *pWUVB, *pBUVB, *pWCAT;
    cudaGetSymbolAddress((void**)&pX,    g_X);
    cudaGetSymbolAddress((void**)&pXAG,  g_XAG);
    cudaGetSymbolAddress((void**)&pXV2,  g_XV2);
    cudaGetSymbolAddress((void**)&pUVA,  g_UVA);
    cudaGetSymbolAddress((void**)&pUVB,  g_UVB);
    cudaGetSymbolAddress((void**)&pH,    g_H);
    cudaGetSymbolAddress((void**)&pCAT,  g_CAT);
    cudaGetSymbolAddress((void**)&pARES, g_ARES);
    cudaGetSymbolAddress((void**)&pWUVA, g_WUVA);
    cudaGetSymbolAddress((void**)&pBUVA, g_BUVA);
    cudaGetSymbolAddress((void**)&pWUVB, g_WUVB);
    cudaGetSymbolAddress((void**)&pBUVB, g_BUVB);
    cudaGetSymbolAddress((void**)&pWCAT, g_WCAT);

    // CSR build
    zero_cnt_kernel<<<NNODES/256, 256>>>();
    hist_kernel<<<NEDGES/256, 256>>>(edge_index);
    scan_kernel<<<1, 1024>>>();
    scatter_kernel<<<NEDGES/256, 256>>>(edge_index, edge_attr);

    // weight prep
    prep_kernel<<<(CC*768 + 255)/256, 256>>>(ecA_W1, ecA_b1, ec1_W1, ec1_b1,
                                             ec2_W1, ec2_b1, ec3_W1, ec3_b1,
                                             sage_Wl, sage_Wr);

    // input projections -> X
    sgemm_kernel<false,false><<<dim3(1, NVROWS/64), 256>>>(x_visual, W011, b011, pX, NVROWS, CC, 1024);
    sgemm_kernel<false,false><<<dim3(1, NAROWS/64), 256>>>(x_audio,  W012, b012, pX + (size_t)NVROWS*CC, NAROWS, CC, 1024);

    // xa_g
    vpa_kernel<<<NNODES/8, 256>>>();

    // u,v for ecA (b1 folded into u bias)
    sgemm_kernel<false,false><<<dim3(2, NNODES/64), 256>>>(pXAG, pWUVA, pBUVA, pUVA, NNODES, 256, CC);

    // ecA edge conv -> a_res (fused fc)
    econv_kernel<<<NNODES/8, 256>>>(pUVA, 256, 0, 128, ecA_W2, ecA_b2, -2, -2,
                                    nullptr, fc_W, fc_b, pARES);

    // xv2
    acv_kernel<<<NNODES/8, 256>>>();

    // u,v for the 3 branches in one GEMM
    sgemm_kernel<false,false><<<dim3(6, NNODES/64), 256>>>(pXV2, pWUVB, pBUVB, pUVB, NNODES, 768, CC);

    const float* W2s[3] = {ec1_W2, ec2_W2, ec3_W2};
    const float* b2s[3] = {ec1_b2, ec2_b2, ec3_b2};
    const int los[3] = { 0, -1, -1};
    const int his[3] = { 1,  0,  1};
    for (int b = 0; b < 3; b++){
        econv_kernel<<<NNODES/8, 256>>>(pUVB, 768, 256*b, 256*b + 128,
                                        W2s[b], b2s[b], los[b], his[b],
                                        pH, nullptr, nullptr, nullptr);
        cat_kernel<<<NOUTR/8, 256>>>(speakers, los[b], his[b]);
        if (b == 0)
            sgemm_kernel<true,false><<<dim3(1, NOUTR/64), 256>>>(pCAT, pWCAT, sage_bl, out, NOUTR, CC, 256);
        else
            sgemm_kernel<true,true ><<<dim3(1, NOUTR/64), 256>>>(pCAT, pWCAT, sage_bl, out, NOUTR, CC, 256);
    }
}

// round 2
// speedup vs baseline: 1.2131x; 1.2131x over previous
#include <cuda_runtime.h>
#include <cstdint>

#define NNODES 32768
#define NEDGES 262144
#define CC 128
#define NOUTR 8192
#define NVROWS 24576
#define NAROWS 8192

// ------------------------- scratch (static device, no allocs) -------------------------
__device__ float g_X  [NNODES*CC];
__device__ float g_XAG[NNODES*CC];
__device__ float g_XV2[NNODES*CC];
__device__ float g_UVA[NNODES*256];
__device__ float g_UVB[NNODES*768];
__device__ float g_H  [NNODES*CC];
__device__ float g_CAT[NOUTR*256];
__device__ float g_ARES[NNODES];
__device__ int   g_cnt[NNODES];
__device__ int   g_rowoff[NNODES+1];
__device__ int   g_cursor[NNODES];
__device__ int   g_esrc[NEDGES];
__device__ int   g_eattr[NEDGES];
__device__ float g_WUVA[CC*256];
__device__ float g_BUVA[256];
__device__ float g_WUVB[CC*768];
__device__ float g_BUVB[768];
__device__ float g_WCAT[256*CC];

// ------------------------- small helpers -------------------------
__device__ __forceinline__ float4 f4max(float4 a, float4 b){
    return make_float4(fmaxf(a.x,b.x),fmaxf(a.y,b.y),fmaxf(a.z,b.z),fmaxf(a.w,b.w));
}
__device__ __forceinline__ float4 f4relu(float4 a){
    return make_float4(fmaxf(a.x,0.f),fmaxf(a.y,0.f),fmaxf(a.z,0.f),fmaxf(a.w,0.f));
}

// ------------------------- CSR build -------------------------
__global__ void zero_cnt_kernel(){
    int i = blockIdx.x*blockDim.x + threadIdx.x;
    if (i < NNODES) g_cnt[i] = 0;
}

__global__ void hist_kernel(const int* __restrict__ ei){
    int e = blockIdx.x*blockDim.x + threadIdx.x;
    if (e < NEDGES) atomicAdd(&g_cnt[ei[NEDGES + e]], 1);
}

__global__ void scan_kernel(){
    __shared__ int sh[1024];
    int tid = threadIdx.x;
    int base = tid * 32;
    int s = 0;
    #pragma unroll
    for (int j = 0; j < 32; j++) s += g_cnt[base + j];
    sh[tid] = s;
    __syncthreads();
    int own = s;
    for (int off = 1; off < 1024; off <<= 1){
        int v = (tid >= off) ? sh[tid - off] : 0;
        __syncthreads();
        sh[tid] += v;
        __syncthreads();
    }
    int run = sh[tid] - own;   // exclusive prefix
    for (int j = 0; j < 32; j++){
        g_rowoff[base + j] = run;
        g_cursor[base + j] = run;
        run += g_cnt[base + j];
    }
    if (tid == 1023) g_rowoff[NNODES] = run;
}

__global__ void scatter_kernel(const int* __restrict__ ei, const int* __restrict__ ea){
    int e = blockIdx.x*blockDim.x + threadIdx.x;
    if (e < NEDGES){
        int d = ei[NEDGES + e];
        int p = atomicAdd(&g_cursor[d], 1);
        g_esrc[p]  = ei[e];
        g_eattr[p] = ea[e];
    }
}

// ------------------------- weight prep -------------------------
__global__ void prep_kernel(const float* __restrict__ ecA_W1, const float* __restrict__ ecA_b1,
                            const float* __restrict__ ec1_W1, const float* __restrict__ ec1_b1,
                            const float* __restrict__ ec2_W1, const float* __restrict__ ec2_b1,
                            const float* __restrict__ ec3_W1, const float* __restrict__ ec3_b1,
                            const float* __restrict__ Wl, const float* __restrict__ Wr){
    int id = blockIdx.x*blockDim.x + threadIdx.x;
    if (id < CC*256){
        int k = id >> 8, c = id & 255;
        float v;
        if (c < 128) v = ecA_W1[k*128 + c] - ecA_W1[(128+k)*128 + c];
        else         v = ecA_W1[(128+k)*128 + (c-128)];
        g_WUVA[k*256 + c] = v;
    }
    if (id < CC*768){
        int k = id / 768, c = id % 768;
        int b = c >> 8, cc = c & 255;
        const float* W1 = (b==0)? ec1_W1 : (b==1)? ec2_W1 : ec3_W1;
        float v;
        if (cc < 128) v = W1[k*128 + cc] - W1[(128+k)*128 + cc];
        else          v = W1[(128+k)*128 + (cc-128)];
        g_WUVB[k*768 + c] = v;
    }
    if (id < 256*CC){
        int k = id >> 7, c = id & 127;
        g_WCAT[id] = (k < 128) ? Wl[k*128 + c] : Wr[(k-128)*128 + c];
    }
    if (id < 256) g_BUVA[id] = (id < 128) ? ecA_b1[id] : 0.f;
    if (id < 768){
        int b = id >> 8, cc = id & 255;
        const float* bb = (b==0)? ec1_b1 : (b==1)? ec2_b1 : ec3_b1;
        g_BUVB[id] = (cc < 128) ? bb[cc] : 0.f;
    }
}

// ------------------------- TF32 tensor-core GEMM (3-pass error-compensated) -------------------------
__device__ __forceinline__ void split_tf32(float x, uint32_t& h, uint32_t& l){
    uint32_t hh; asm("cvt.rna.tf32.f32 %0, %1;" : "=r"(hh) : "f"(x));
    float lf = x - __uint_as_float(hh);
    uint32_t ll; asm("cvt.rna.tf32.f32 %0, %1;" : "=r"(ll) : "f"(lf));
    h = hh; l = ll;
}

__device__ __forceinline__ void mma8(float* c, const uint32_t* a, uint32_t b0, uint32_t b1){
    asm volatile("mma.sync.aligned.m16n8k8.row.col.f32.tf32.tf32.f32 "
        "{%0,%1,%2,%3},{%4,%5,%6,%7},{%8,%9},{%0,%1,%2,%3};"
        : "+f"(c[0]),"+f"(c[1]),"+f"(c[2]),"+f"(c[3])
        : "r"(a[0]),"r"(a[1]),"r"(a[2]),"r"(a[3]),"r"(b0),"r"(b1));
}

// Block tile 128x128, BK=16. 8 warps (2m x 4n), warp tile 64x32.
// Smem word-plane layout: As[tile(16)][word(8)][lane(32)], Bs[tile(32)][word(4)][lane(32)]
template<bool RELU, bool ACC>
__device__ __forceinline__ void tgemm_body(const float* __restrict__ A,
                                           const float* __restrict__ B,
                                           const float* __restrict__ bias,
                                           float* __restrict__ C,
                                           int N, int K,
                                           int m0, int n0,
                                           uint32_t* As, uint32_t* Bs){
    int tid = threadIdx.x;
    int wid = tid>>5, lane = tid&31;
    int g = lane>>2, t = lane&3;
    int mtb = (wid>>2)*4;       // m-tile base (16-row tiles)
    int ntb = (wid&3)*4;        // n-tile base (8-col tiles)
    float acc[4][4][4];
    #pragma unroll
    for(int i=0;i<4;i++)
        #pragma unroll
        for(int j=0;j<4;j++)
            #pragma unroll
            for(int r=0;r<4;r++) acc[i][j][r]=0.f;

    for (int k0=0; k0<K; k0+=16){
        // ---- stage A (512 lane-slots) ----
        #pragma unroll
        for (int s0=0; s0<2; s0++){
            int s = tid + s0*256;
            int mt = s>>6, kt=(s>>5)&1, ln=s&31;
            int gg=ln>>2, tt=ln&3;
            const float* p  = A + (size_t)(m0+mt*16+gg)*K + (k0+kt*8+tt);
            const float* p8 = p + (size_t)8*K;
            float a0=p[0], a2=p[4], a1=p8[0], a3=p8[4];
            uint32_t h0,l0,h1,l1,h2,l2,h3,l3;
            split_tf32(a0,h0,l0); split_tf32(a1,h1,l1);
            split_tf32(a2,h2,l2); split_tf32(a3,h3,l3);
            uint32_t* d = As + (mt*2+kt)*256 + ln;
            d[0]=h0; d[32]=h1; d[64]=h2; d[96]=h3;
            d[128]=l0; d[160]=l1; d[192]=l2; d[224]=l3;
        }
        // ---- stage B (1024 lane-slots) ----
        #pragma unroll
        for (int s0=0; s0<4; s0++){
            int s = tid + s0*256;
            int nt = s>>6, kt=(s>>5)&1, ln=s&31;
            int gg=ln>>2, tt=ln&3;
            const float* p = B + (size_t)(k0+kt*8+tt)*N + (n0+nt*8+gg);
            float b0=p[0], b1=p[(size_t)4*N];
            uint32_t h0,l0,h1,l1;
            split_tf32(b0,h0,l0); split_tf32(b1,h1,l1);
            uint32_t* d = Bs + (nt*2+kt)*128 + ln;
            d[0]=h0; d[32]=h1; d[64]=l0; d[96]=l1;
        }
        __syncthreads();
        #pragma unroll
        for (int kt=0; kt<2; kt++){
            uint32_t ah[4][4], al[4][4];
            #pragma unroll
            for (int i=0;i<4;i++){
                const uint32_t* p = As + ((mtb+i)*2+kt)*256 + lane;
                #pragma unroll
                for (int r=0;r<4;r++){ ah[i][r]=p[r*32]; al[i][r]=p[128+r*32]; }
            }
            #pragma unroll
            for (int j=0;j<4;j++){
                const uint32_t* p = Bs + ((ntb+j)*2+kt)*128 + lane;
                uint32_t b0h=p[0], b1h=p[32], b0l=p[64], b1l=p[96];
                #pragma unroll
                for (int i=0;i<4;i++){
                    mma8(acc[i][j], ah[i], b0h, b1h);
                    mma8(acc[i][j], al[i], b0h, b1h);
                    mma8(acc[i][j], ah[i], b0l, b1l);
                }
            }
        }
        __syncthreads();
    }
    // ---- epilogue ----
    #pragma unroll
    for (int i=0;i<4;i++){
        int row = m0 + (mtb+i)*16 + g;
        #pragma unroll
        for (int j=0;j<4;j++){
            int col = n0 + (ntb+j)*8 + 2*t;
            float bz0 = bias[col], bz1 = bias[col+1];
            #pragma unroll
            for (int h=0;h<2;h++){
                float v0 = acc[i][j][h*2+0] + bz0;
                float v1 = acc[i][j][h*2+1] + bz1;
                if (RELU){ v0=fmaxf(v0,0.f); v1=fmaxf(v1,0.f); }
                float* cp = C + (size_t)(row + h*8)*N + col;
                if (ACC){ cp[0]+=v0; cp[1]+=v1; }
                else    { cp[0]=v0;  cp[1]=v1; }
            }
        }
    }
}

template<bool RELU, bool ACC>
__global__ void __launch_bounds__(256) tgemm_kernel(const float* __restrict__ A,
                                                    const float* __restrict__ B,
                                                    const float* __restrict__ bias,
                                                    float* __restrict__ C,
                                                    int N, int K){
    __shared__ uint32_t As[4096], Bs[4096];
    tgemm_body<RELU,ACC>(A,B,bias,C,N,K, blockIdx.y*128, blockIdx.x*128, As, Bs);
}

__global__ void __launch_bounds__(256) tgemm_proj_kernel(const float* __restrict__ Av,
                                                         const float* __restrict__ Aa,
                                                         const float* __restrict__ Wv,
                                                         const float* __restrict__ Wa,
                                                         const float* __restrict__ bv,
                                                         const float* __restrict__ ba,
                                                         float* __restrict__ C){
    __shared__ uint32_t As[4096], Bs[4096];
    if (blockIdx.z == 0){
        tgemm_body<false,false>(Av, Wv, bv, C, 128, 1024, blockIdx.y*128, 0, As, Bs);
    } else {
        if (blockIdx.y >= NAROWS/128) return;
        tgemm_body<false,false>(Aa, Wa, ba, C + (size_t)NVROWS*CC, 128, 1024, blockIdx.y*128, 0, As, Bs);
    }
}

// ------------------------- per-node graph kernels (warp per node, CSR) -------------------------
__global__ void vpa_kernel(){
    int w = threadIdx.x >> 5, lane = threadIdx.x & 31;
    int node = blockIdx.x * 8 + w;
    if (node >= NNODES) return;
    const float4* X4 = (const float4*)g_X;
    float4 xd = X4[(size_t)node*32 + lane];
    float4 m = make_float4(-1e30f,-1e30f,-1e30f,-1e30f);
    bool found = false;
    int p = g_rowoff[node], pe = g_rowoff[node+1];
    for (; p < pe; p++){
        if (g_eattr[p] == -3){
            float4 xs = X4[(size_t)g_esrc[p]*32 + lane];
            m = f4max(m, make_float4(xd.x+xs.x, xd.y+xs.y, xd.z+xs.z, xd.w+xs.w));
            found = true;
        }
    }
    float4 o = found ? f4relu(m) : make_float4(0.f,0.f,0.f,0.f);
    ((float4*)g_XAG)[(size_t)node*32 + lane] = o;
}

__global__ void acv_kernel(){
    int w = threadIdx.x >> 5, lane = threadIdx.x & 31;
    int node = blockIdx.x * 8 + w;
    if (node >= NNODES) return;
    const float4* X4 = (const float4*)g_X;
    float4 xd = X4[(size_t)node*32 + lane];
    float4 acc = make_float4(0.f,0.f,0.f,0.f);
    int p = g_rowoff[node], pe = g_rowoff[node+1];
    for (; p < pe; p++){
        if (g_eattr[p] == 3){
            int s = g_esrc[p];
            float wgt = g_ARES[s];
            float4 xs = X4[(size_t)s*32 + lane];
            acc.x += wgt*xs.x + xd.x;
            acc.y += wgt*xs.y + xd.y;
            acc.z += wgt*xs.z + xd.z;
            acc.w += wgt*xs.w + xd.w;
        }
    }
    ((float4*)g_XV2)[(size_t)node*32 + lane] = f4relu(acc);
}

template<int CNT>
__device__ __forceinline__ void kdot(const float* __restrict__ W2, int lane,
                                     const float (*ts)[CC], float4 acc[4]){
    #pragma unroll 4
    for (int k = 0; k < CC; k++){
        float4 wv = __ldg((const float4*)(W2 + k*CC + lane*4));
        #pragma unroll
        for (int e = 0; e < CNT; e++){
            float t = ts[e][k];
            acc[e].x += wv.x * t;
            acc[e].y += wv.y * t;
            acc[e].z += wv.z * t;
            acc[e].w += wv.w * t;
        }
    }
}

__global__ void __launch_bounds__(256) econv_kernel(const float* __restrict__ UV, int ustride,
                                                    int uoff, int voff,
                                                    const float* __restrict__ W2,
                                                    const float* __restrict__ b2,
                                                    int lo, int hi,
                                                    float* __restrict__ Hout,
                                                    const float* __restrict__ fcW,
                                                    const float* __restrict__ fcb,
                                                    float* __restrict__ ares){
    __shared__ float ts[8][4][CC];
    int w = threadIdx.x >> 5, lane = threadIdx.x & 31;
    int node = blockIdx.x * 8 + w;
    if (node >= NNODES) return;
    float4 u = *(const float4*)(UV + (size_t)node*ustride + uoff + lane*4);
    float4 macc = make_float4(-1e30f,-1e30f,-1e30f,-1e30f);
    bool found = false;
    int p = g_rowoff[node], pe = g_rowoff[node+1];
    while (p < pe){
        int srcs[4]; int cnt = 0;
        while (p < pe && cnt < 4){
            int a = g_eattr[p];
            if (a >= lo && a <= hi) srcs[cnt++] = g_esrc[p];
            p++;
        }
        if (cnt == 0) break;
        for (int e = 0; e < cnt; e++){
            float4 v = *(const float4*)(UV + (size_t)srcs[e]*ustride + voff + lane*4);
            float4 t = f4relu(make_float4(u.x+v.x, u.y+v.y, u.z+v.z, u.w+v.w));
            *(float4*)&ts[w][e][lane*4] = t;
        }
        __syncwarp();
        float4 acc[4];
        #pragma unroll
        for (int e = 0; e < 4; e++) acc[e] = make_float4(0.f,0.f,0.f,0.f);
        const float (*tw)[CC] = (const float (*)[CC])ts[w];
        switch (cnt){
            case 1: kdot<1>(W2, lane, tw, acc); break;
            case 2: kdot<2>(W2, lane, tw, acc); break;
            case 3: kdot<3>(W2, lane, tw, acc); break;
            default: kdot<4>(W2, lane, tw, acc); break;
        }
        for (int e = 0; e < cnt; e++) macc = f4max(macc, acc[e]);
        found = true;
        __syncwarp();
    }
    float4 r;
    if (found){
        float4 bb = *(const float4*)(b2 + lane*4);
        r = f4relu(make_float4(macc.x+bb.x, macc.y+bb.y, macc.z+bb.z, macc.w+bb.w));
    } else {
        r = make_float4(0.f,0.f,0.f,0.f);
    }
    if (Hout) *(float4*)(Hout + (size_t)node*CC + lane*4) = r;
    if (ares){
        float part = r.x*fcW[lane*4] + r.y*fcW[lane*4+1] + r.z*fcW[lane*4+2] + r.w*fcW[lane*4+3];
        #pragma unroll
        for (int o = 16; o > 0; o >>= 1) part += __shfl_down_sync(0xffffffffu, part, o);
        if (lane == 0) ares[node] = part + fcb[0];
    }
}

__global__ void cat_kernel(const int* __restrict__ spkp, int lo, int hi){
    int w = threadIdx.x >> 5, lane = threadIdx.x & 31;
    int r = blockIdx.x * 8 + w;
    if (r >= NOUTR) return;
    int spk = spkp ? spkp[0] : 3;
    int node = (r >> 7) * spk * 128 + (r & 127);
    const float4* H4 = (const float4*)g_H;
    float4 s = make_float4(0.f,0.f,0.f,0.f);
    int cnt = 0;
    int p = g_rowoff[node], pe = g_rowoff[node+1];
    for (; p < pe; p++){
        int a = g_eattr[p];
        if (a >= lo && a <= hi){
            float4 hs = H4[(size_t)g_esrc[p]*32 + lane];
            s.x += hs.x; s.y += hs.y; s.z += hs.z; s.w += hs.w;
            cnt++;
        }
    }
    float inv = cnt ? 1.f/(float)cnt : 0.f;
    float4* C4 = (float4*)g_CAT;
    C4[(size_t)r*64 + lane]      = make_float4(s.x*inv, s.y*inv, s.z*inv, s.w*inv);
    C4[(size_t)r*64 + 32 + lane] = H4[(size_t)node*32 + lane];
}

// ------------------------- launch -------------------------
extern "C" void kernel_launch(void* const* d_in, const int* in_sizes, int n_in,
                              void* d_out, int out_size){
    const float* x_visual = (const float*)d_in[0];
    const float* x_audio  = (const float*)d_in[1];
    const float* W011 = (const float*)d_in[2];
    const float* b011 = (const float*)d_in[3];
    const float* W012 = (const float*)d_in[4];
    const float* b012 = (const float*)d_in[5];
    const float* ecA_W1 = (const float*)d_in[6];
    const float* ecA_b1 = (const float*)d_in[7];
    const float* ecA_W2 = (const float*)d_in[8];
    const float* ecA_b2 = (const float*)d_in[9];
    const float* ec1_W1 = (const float*)d_in[10];
    const float* ec1_b1 = (const float*)d_in[11];
    const float* ec1_W2 = (const float*)d_in[12];
    const float* ec1_b2 = (const float*)d_in[13];
    const float* ec2_W1 = (const float*)d_in[14];
    const float* ec2_b1 = (const float*)d_in[15];
    const float* ec2_W2 = (const float*)d_in[16];
    const float* ec2_b2 = (const float*)d_in[17];
    const float* ec3_W1 = (const float*)d_in[18];
    const float* ec3_b1 = (const float*)d_in[19];
    const float* ec3_W2 = (const float*)d_in[20];
    const float* ec3_b2 = (const float*)d_in[21];
    const float* sage_Wl = (const float*)d_in[22];
    const float* sage_bl = (const float*)d_in[23];
    const float* sage_Wr = (const float*)d_in[24];
    const float* fc_W = (const float*)d_in[25];
    const float* fc_b = (const float*)d_in[26];
    const int* edge_index = (const int*)d_in[27];
    const int* edge_attr  = (const int*)d_in[28];
    const int* speakers   = (n_in > 29) ? (const int*)d_in[29] : nullptr;
    float* out = (float*)d_out;

    float *pX, *pXAG, *pXV2, *pUVA, *pUVB, *pH, *pCAT, *pARES;
    float *pWUVA, *pBUVA, *pWUVB, *pBUVB, *pWCAT;
    cudaGetSymbolAddress((void**)&pX,    g_X);
    cudaGetSymbolAddress((void**)&pXAG,  g_XAG);
    cudaGetSymbolAddress((void**)&pXV2,  g_XV2);
    cudaGetSymbolAddress((void**)&pUVA,  g_UVA);
    cudaGetSymbolAddress((void**)&pUVB,  g_UVB);
    cudaGetSymbolAddress((void**)&pH,    g_H);
    cudaGetSymbolAddress((void**)&pCAT,  g_CAT);
    cudaGetSymbolAddress((void**)&pARES, g_ARES);
    cudaGetSymbolAddress((void**)&pWUVA, g_WUVA);
    cudaGetSymbolAddress((void**)&pBUVA, g_BUVA);
    cudaGetSymbolAddress((void**)&pWUVB, g_WUVB);
    cudaGetSymbolAddress((void**)&pBUVB, g_BUVB);
    cudaGetSymbolAddress((void**)&pWCAT, g_WCAT);

    // CSR build
    zero_cnt_kernel<<<NNODES/256, 256>>>();
    hist_kernel<<<NEDGES/256, 256>>>(edge_index);
    scan_kernel<<<1, 1024>>>();
    scatter_kernel<<<NEDGES/256, 256>>>(edge_index, edge_attr);

    // weight prep
    prep_kernel<<<(CC*768 + 255)/256, 256>>>(ecA_W1, ecA_b1, ec1_W1, ec1_b1,
                                             ec2_W1, ec2_b1, ec3_W1, ec3_b1,
                                             sage_Wl, sage_Wr);

    // input projections -> X (fused visual+audio, tensor cores)
    tgemm_proj_kernel<<<dim3(1, NVROWS/128, 2), 256>>>(x_visual, x_audio, W011, W012, b011, b012, pX);

    // xa_g
    vpa_kernel<<<NNODES/8, 256>>>();

    // u,v for ecA
    tgemm_kernel<false,false><<<dim3(2, NNODES/128), 256>>>(pXAG, pWUVA, pBUVA, pUVA, 256, CC);

    // ecA edge conv -> a_res (fused fc)
    econv_kernel<<<NNODES/8, 256>>>(pUVA, 256, 0, 128, ecA_W2, ecA_b2, -2, -2,
                                    nullptr, fc_W, fc_b, pARES);

    // xv2
    acv_kernel<<<NNODES/8, 256>>>();

    // u,v for the 3 branches
    tgemm_kernel<false,false><<<dim3(6, NNODES/128), 256>>>(pXV2, pWUVB, pBUVB, pUVB, 768, CC);

    const float* W2s[3] = {ec1_W2, ec2_W2, ec3_W2};
    const float* b2s[3] = {ec1_b2, ec2_b2, ec3_b2};
    const int los[3] = { 0, -1, -1};
    const int his[3] = { 1,  0,  1};
    for (int b = 0; b < 3; b++){
        econv_kernel<<<NNODES/8, 256>>>(pUVB, 768, 256*b, 256*b + 128,
                                        W2s[b], b2s[b], los[b], his[b],
                                        pH, nullptr, nullptr, nullptr);
        cat_kernel<<<NOUTR/8, 256>>>(speakers, los[b], his[b]);
        if (b == 0)
            tgemm_kernel<true,false><<<dim3(1, NOUTR/128), 256>>>(pCAT, pWCAT, sage_bl, out, CC, 256);
        else
            tgemm_kernel<true,true ><<<dim3(1, NOUTR/128), 256>>>(pCAT, pWCAT, sage_bl, out, CC, 256);
    }
}